// round 17
// baseline (speedup 1.0000x reference)
#include <cuda_runtime.h>

// CostVolume3D: B=8, H=128, W=256, C=8, D=23.
// Half-group per thread (j=0..11 / j=12..22), compile-time L-phase schedule.
// NEW: constexpr permutation sorts each block's 256 half-groups so that pure
// "lean" warps (no row crossing, no clamping -> exactly ONE tap flip, v==8,
// W-window only 2 wide, no pixel bookkeeping) run a stripped ~22-instr step;
// general warps run the proven R16 chain. Lean iff start residue
// s = 23m mod 256 in [12,232] (h=0) / [0,221] (h=1); block residue pattern
// depends only on blockIdx parity (23*128 = 128 mod 256).

#define W_ 256
#define D_ 23
static constexpr int NF  = 8 * 128 * 256 * 8;    // 2,097,152
static constexpr int NW  = 8 * 128 * 256;        // 262,144 groups
static constexpr int TPB = 256;
static constexpr int GPB = 128;                  // groups per block
static constexpr unsigned LASTF = (unsigned)(NF - 1);

// ---------- constexpr permutation: lean-first ordering per (parity, half) ----
struct Perm {
    unsigned char idx[2][2][GPB];
    int cnt[2][2];
};
constexpr bool is_lean(int s, int h) {
    return (h == 0) ? (s >= 12 && s <= 232) : (s <= 221);
}
constexpr Perm gen_perm() {
    Perm P{};
    for (int p = 0; p < 2; p++)
        for (int h = 0; h < 2; h++) {
            int n = 0;
            for (int i = 0; i < GPB; i++)
                if (is_lean((128 * p + 23 * i) & 255, h))
                    P.idx[p][h][n++] = (unsigned char)i;
            P.cnt[p][h] = n;
            for (int i = 0; i < GPB; i++)
                if (!is_lean((128 * p + 23 * i) & 255, h))
                    P.idx[p][h][n++] = (unsigned char)i;
        }
    return P;
}
__device__ constexpr Perm d_perm = gen_perm();

// ------------------------------- general path (R16, proven) -----------------
struct GState {
    int   w2v, base, s, x0v, iW, iA;
    float w, frac, fm1, r0f, W0, W1, W2, A0, A1, dA;
};

static __device__ __forceinline__ void tap_init(
    const float* __restrict__ fr, GState& g, int w2v_in)
{
    const float disp = g.w - (float)(g.s - 11);
    const float xq   = (float)w2v_in - disp;
    const float x0f  = floorf(xq);
    g.frac = xq - x0f;
    g.fm1  = g.frac - 1.0f;
    g.x0v  = (int)x0f;
    const int x0i = min(max(g.x0v, 0), W_ - 1);
    const unsigned p0 = (unsigned)(g.base + x0i) * 8u;
    const unsigned i0 = p0 / 23u;
    g.r0f = (float)(int)(p0 - i0 * 23u);
    g.iW  = (int)i0;
    g.W0 = __ldg(fr + g.iW);
    g.W1 = __ldg(fr + min((unsigned)g.iW + 1u, LASTF));
    g.W2 = __ldg(fr + min((unsigned)g.iW + 2u, LASTF));
}

template <int J0>
static __device__ __forceinline__ void group_init(
    const float* __restrict__ fl, const float* __restrict__ fr,
    const float* __restrict__ wf, int m, GState& g)
{
    constexpr int KJ = (8 * J0) / 23;
    const int qs = m * 23 + J0;
    g.w    = __ldg(wf + m);
    g.w2v  = qs & (W_ - 1);
    g.base = qs - g.w2v;
    const int x = qs >> 15;
    g.s = x - 23 * ((x * 179) >> 12);
    g.iA = m * 8;
    g.A0 = __ldg(fl + g.iA + KJ);
    g.A1 = __ldg(fl + g.iA + KJ + 1);
    g.dA = g.A1 - g.A0;
    tap_init(fr, g, g.w2v);
}

template <int J, int JLAST>
static __device__ __forceinline__ void step(
    const float* __restrict__ fl, const float* __restrict__ fr,
    GState& g, float* __restrict__ sb)
{
    constexpr int   RL = (8 * J) % 23;
    constexpr float TL = (23 - RL < 8) ? (float)(23 - RL) : 8.0f;
    constexpr bool ADV = (RL >= 15) && (J != JLAST);
    constexpr int  ANX = (8 * J) / 23 + 2;

    if (g.w2v == W_) {
        g.w2v = 0; g.base += W_;
        if ((g.base & 32767) == 0) g.s = (g.s == 22) ? 0 : g.s + 1;
        tap_init(fr, g, 0);
    }

    const bool  e   = (g.x0v < W_ - 1);
    const bool  hi0 = (g.r0f >= 15.0f);
    const float t23 = 23.0f - g.r0f;
    const float u = hi0 ? t23 : (e ? fminf(15.0f - g.r0f, 8.0f) : 8.0f);
    const float v = (!e && hi0) ? t23 : 8.0f;

    const float dW01 = g.W1 - g.W0;
    const float dW12 = g.W2 - g.W1;
    const bool  inc  = e && hi0;
    const float D0 = g.fm1 * dW01;
    const float D1 = -g.frac * (inc ? dW12 : dW01);
    const float du = hi0 ? D0 : D1;
    const float dv = hi0 ? D1 : D0;
    const float be = g.A0 - g.W0;
    const float e0 = inc ? fmaf(-g.frac, dW01, be) : be;

    float acc;
    if (TL >= 8.0f) {
        const float g1 = e0 + du;
        const float g2 = g1 + dv;
        acc = u * fabsf(e0);
        acc = fmaf(v - u,    fabsf(g1), acc);
        acc = fmaf(8.0f - v, fabsf(g2), acc);
    } else {
        const float a = fminf(TL, u);
        const float c = fmaxf(TL, v);
        const float b = ((TL + u) + v) - (a + c);
        const float g3 = e0 + (g.dA + (du + dv));
        const float g1 = e0 + ((u <= TL) ? du : g.dA);
        const float g2 = g3 - ((v <= TL) ? g.dA : dv);
        acc = a * fabsf(e0);
        acc = fmaf(b - a,    fabsf(g1), acc);
        acc = fmaf(c - b,    fabsf(g2), acc);
        acc = fmaf(8.0f - c, fabsf(g3), acc);
    }
    sb[J] = acc;

    const float nr0 = hi0 ? (g.r0f - 15.0f) : (g.r0f + 8.0f);
    g.x0v += 1;
    if ((unsigned)(g.x0v - 1) < (unsigned)(W_ - 1)) {
        g.r0f = nr0;
        if (hi0) {
            g.iW += 1;
            g.W0 = g.W1; g.W1 = g.W2;
            g.W2 = __ldg(fr + min((unsigned)g.iW + 2u, LASTF));
        }
    }
    g.w2v += 1;

    if (ADV) {
        g.A0 = g.A1;
        g.A1 = __ldg(fl + min((unsigned)(g.iA + ANX), LASTF));
        g.dA = g.A1 - g.A0;
    }
}

template <int J, int JEND>
static __device__ __forceinline__ void run_steps(
    const float* __restrict__ fl, const float* __restrict__ fr,
    GState& g, float* __restrict__ sb)
{
    if constexpr (J < JEND) {
        step<J, JEND - 1>(fl, fr, g, sb);
        run_steps<J + 1, JEND>(fl, fr, g, sb);
    }
}

// ------------------------------- lean path -----------------------------------
// Interior half-group: no crossing, no clamp. Exactly one tap flip at u,
// v == 8, W2 never read (2-wide W window), no pixel bookkeeping.
struct LState {
    int   iW, iA;
    float frac, fm1, nfr, r0f, W0, W1, A0, A1, dA;
};

template <int J0>
static __device__ __forceinline__ void lean_init(
    const float* __restrict__ fl, const float* __restrict__ fr,
    const float* __restrict__ wf, int m, LState& g)
{
    constexpr int KJ = (8 * J0) / 23;
    const int qs  = m * 23 + J0;
    const int w2v = qs & (W_ - 1);
    const int x   = qs >> 15;
    const int s   = x - 23 * ((x * 179) >> 12);
    const float w = __ldg(wf + m);
    const float disp = w - (float)(s - 11);
    const float xq   = (float)w2v - disp;
    const float x0f  = floorf(xq);
    g.frac = xq - x0f;
    g.fm1  = g.frac - 1.0f;
    g.nfr  = -g.frac;
    const int x0v = (int)x0f;                     // guaranteed in [0,254]
    const unsigned p0 = (unsigned)((qs - w2v) + x0v) * 8u;
    const unsigned i0 = p0 / 23u;
    g.r0f = (float)(int)(p0 - i0 * 23u);
    g.iW  = (int)i0;
    g.W0 = __ldg(fr + g.iW);
    g.W1 = __ldg(fr + min((unsigned)g.iW + 1u, LASTF));
    g.iA = m * 8;
    g.A0 = __ldg(fl + g.iA + KJ);
    g.A1 = __ldg(fl + g.iA + KJ + 1);
    g.dA = g.A1 - g.A0;
}

template <int J, bool LASTSTEP>
static __device__ __forceinline__ void lean_step(
    const float* __restrict__ fl, const float* __restrict__ fr,
    LState& g, float* __restrict__ sb)
{
    constexpr int   RL = (8 * J) % 23;
    constexpr float TL = (23 - RL < 8) ? (float)(23 - RL) : 8.0f;
    constexpr bool ADV = (RL >= 15) && !LASTSTEP;
    constexpr int  ANX = (8 * J) / 23 + 2;

    const bool  hi0 = (g.r0f >= 15.0f);
    const float u  = hi0 ? (23.0f - g.r0f) : fminf(15.0f - g.r0f, 8.0f);
    const float dW = g.W1 - g.W0;
    const float du = (hi0 ? g.fm1 : g.nfr) * dW;
    const float be = g.A0 - g.W0;
    const float e0 = hi0 ? fmaf(g.nfr, dW, be) : be;

    float acc;
    if constexpr (TL >= 8.0f) {                   // only the tap flip
        const float g1 = e0 + du;
        acc = fmaf(8.0f - u, fabsf(g1), u * fabsf(e0));
    } else {                                      // tap flip + L flip
        const float a  = fminf(TL, u);
        const float b  = fmaxf(TL, u);
        const float g2 = e0 + (g.dA + du);
        const float g1 = e0 + ((u <= TL) ? du : g.dA);
        acc = a * fabsf(e0);
        acc = fmaf(b - a,    fabsf(g1), acc);
        acc = fmaf(8.0f - b, fabsf(g2), acc);
    }
    sb[J] = acc;

    if constexpr (!LASTSTEP) {
        g.r0f = hi0 ? (g.r0f - 15.0f) : (g.r0f + 8.0f);
        if (hi0) {
            g.iW += 1;
            g.W0 = g.W1;
            g.W1 = __ldg(fr + min((unsigned)g.iW + 1u, LASTF));
        }
        if constexpr (ADV) {
            g.A0 = g.A1;
            g.A1 = __ldg(fl + min((unsigned)(g.iA + ANX), LASTF));
            g.dA = g.A1 - g.A0;
        }
    }
}

template <int J, int JEND>
static __device__ __forceinline__ void run_lean(
    const float* __restrict__ fl, const float* __restrict__ fr,
    LState& g, float* __restrict__ sb)
{
    if constexpr (J < JEND) {
        lean_step<J, J == JEND - 1>(fl, fr, g, sb);
        run_lean<J + 1, JEND>(fl, fr, g, sb);
    }
}

// ------------------------------- kernel --------------------------------------
__global__ void __launch_bounds__(TPB)
costvol3d_kernel(const float* __restrict__ fl,
                 const float* __restrict__ fr,
                 const float* __restrict__ wf,
                 float* __restrict__ out)
{
    __shared__ float sbuf[GPB * D_];
    const int tid  = threadIdx.x;
    const int lane = tid & 31;
    const int warp = tid >> 5;
    const int M0   = blockIdx.x * GPB;
    const int p    = blockIdx.x & 1;

    const int h    = warp >> 2;                  // warps 0-3: h0, 4-7: h1
    const int sub  = warp & 3;
    const int slot = sub * 32 + lane;
    const int i    = d_perm.idx[p][h][slot];
    const int m    = M0 + i;
    float* sb = sbuf + i * D_;
    const bool leanw = ((sub + 1) * 32 <= d_perm.cnt[p][h]);  // warp-uniform

    if (h == 0) {
        if (leanw) {
            LState g; lean_init<0>(fl, fr, wf, m, g);
            run_lean<0, 12>(fl, fr, g, sb);
        } else {
            GState g; group_init<0>(fl, fr, wf, m, g);
            run_steps<0, 12>(fl, fr, g, sb);
        }
    } else {
        if (leanw) {
            LState g; lean_init<12>(fl, fr, wf, m, g);
            run_lean<12, 23>(fl, fr, g, sb);
        } else {
            GState g; group_init<12>(fl, fr, wf, m, g);
            run_steps<12, 23>(fl, fr, g, sb);
        }
    }

    __syncthreads();

    const float4* s4 = reinterpret_cast<const float4*>(sbuf);
    float4* o4 = reinterpret_cast<float4*>(out + M0 * D_);
    constexpr int NV4 = GPB * D_ / 4;            // 736
#pragma unroll
    for (int k = 0; k < (NV4 + TPB - 1) / TPB; k++) {
        const int idx = k * TPB + tid;
        if (idx < NV4) o4[idx] = s4[idx];
    }
}

extern "C" void kernel_launch(void* const* d_in, const int* in_sizes, int n_in,
                              void* d_out, int out_size)
{
    const float* feat_l = (const float*)d_in[0];
    const float* feat_r = (const float*)d_in[1];
    const float* wflow  = (const float*)d_in[2];
    float* out = (float*)d_out;

    costvol3d_kernel<<<NW / GPB, TPB>>>(feat_l, feat_r, wflow, out);
}